// round 8
// baseline (speedup 1.0000x reference)
#include <cuda_runtime.h>
#include <cstdint>
#include <cstddef>

// ---------------------------------------------------------------------------
// NeuralODE Dopri5. GEMMs: mma.sync m16n8k8 TF32, 3xTF32 split.
// A: LDG -> tf32split -> STS. W: pre-split hi/lo via cp.async.
// BK=32 double-buffered stages, ldmatrix fragments with register double
// buffering over k-slices, 2 CTAs/SM for cross-CTA latency overlap.
// RK combine fused into layer-3 epilogue.
// ---------------------------------------------------------------------------

#define BB 1024
#define DD 256
#define HH 512
#define N_STEPS 40
#define HSTEP 0.25f

__device__ float g_y   [BB * DD];
__device__ float g_ycmb[BB * DD];
__device__ float g_k [6][BB * DD];
__device__ float g_h1[BB * HH];
__device__ float g_h2[BB * HH];
__device__ float g_W1hi[HH * DD], g_W1lo[HH * DD];
__device__ float g_W2hi[HH * HH], g_W2lo[HH * HH];
__device__ float g_W3hi[DD * HH], g_W3lo[DD * HH];

struct Epi {
    const float* yin;
    const float* ks[4];
    float        cks[4];
    int          nks;
    float        cself;
    float*       aux;
    float*       emit;
    int          t;
};

// ----------------------------- helpers -------------------------------------
__device__ __forceinline__ uint32_t smem_u32(const void* p) {
    uint32_t a;
    asm("{ .reg .u64 t; cvta.to.shared.u64 t, %1; cvt.u32.u64 %0, t; }"
        : "=r"(a) : "l"(p));
    return a;
}
__device__ __forceinline__ void tf32split(float x, uint32_t& hi, uint32_t& lo) {
    uint32_t h; asm("cvt.rna.tf32.f32 %0, %1;" : "=r"(h) : "f"(x));
    float r = x - __uint_as_float(h);
    asm("cvt.rna.tf32.f32 %0, %1;" : "=r"(lo) : "f"(r));
    hi = h;
}
__device__ __forceinline__ void sts128(uint32_t a, uint32_t x, uint32_t y,
                                       uint32_t z, uint32_t w) {
    asm volatile("st.shared.v4.b32 [%0], {%1,%2,%3,%4};"
                 :: "r"(a), "r"(x), "r"(y), "r"(z), "r"(w) : "memory");
}
__device__ __forceinline__ void cp16(uint32_t d, const float* s) {
    asm volatile("cp.async.cg.shared.global [%0], [%1], 16;"
                 :: "r"(d), "l"(s) : "memory");
}
__device__ __forceinline__ void ldm4(uint32_t* r, uint32_t addr) {
    asm volatile("ldmatrix.sync.aligned.m8n8.x4.shared.b16 {%0,%1,%2,%3}, [%4];"
                 : "=r"(r[0]), "=r"(r[1]), "=r"(r[2]), "=r"(r[3]) : "r"(addr));
}
__device__ __forceinline__ void mma8(float* d, const uint32_t* a,
                                     uint32_t b0, uint32_t b1) {
    asm volatile(
        "mma.sync.aligned.m16n8k8.row.col.f32.tf32.tf32.f32 "
        "{%0,%1,%2,%3}, {%4,%5,%6,%7}, {%8,%9}, {%0,%1,%2,%3};"
        : "+f"(d[0]), "+f"(d[1]), "+f"(d[2]), "+f"(d[3])
        : "r"(a[0]), "r"(a[1]), "r"(a[2]), "r"(a[3]), "r"(b0), "r"(b1));
}

// ---------------------------------------------------------------------------
// GEMM: C[M,N] = act(A @ W^T + bias).
// CTA tile BM x BN, warp grid (BM/16) x WGN, warp tile 16x16.
// BK=32 double buffered; smem rows 128B, XOR swizzle col4 ^= 4*(row&7).
// Stage layout: Ahi[AB] Alo[AB] Whi[WB] Wlo[WB]; AB=BM*128, WB=BN*128.
// MODE 0: relu fp32 store. MODE 1: linear store + fused RK-combine epilogue.
// ---------------------------------------------------------------------------
template<int BM, int BN, int WGN, int MODE>
__global__ __launch_bounds__((BM / 16) * WGN * 32, 2)
void gemm_tc(const float* __restrict__ A,
             const float* __restrict__ Whi, const float* __restrict__ Wlo,
             const float* __restrict__ bias, float* __restrict__ C,
             int K, int N, Epi ep)
{
    constexpr int NT = (BM / 16) * WGN * 32;
    constexpr uint32_t AB = (uint32_t)BM * 128;
    constexpr uint32_t WB = (uint32_t)BN * 128;
    constexpr uint32_t WOFF = 2 * AB;
    constexpr uint32_t STRIDE = 2 * AB + 2 * WB;
    constexpr int AQ = BM * 8 / NT;            // A 16B-chunks per thread
    constexpr int WQ = BN * 8 / NT;            // W 16B-chunks per thread

    extern __shared__ float smem[];
    const uint32_t sb = smem_u32(smem);
    const int tid  = threadIdx.x;
    const int warp = tid >> 5, lane = tid & 31;
    const int wM = warp / WGN, wN = warp % WGN;
    const int g = lane >> 2, c = lane & 3;
    const int m0 = blockIdx.y * BM, n0 = blockIdx.x * BN;

    // loader geometry
    const int lr  = tid >> 3;
    const int lc4 = (tid & 7) * 4;
    const uint32_t ssc = ((uint32_t)lc4 ^ (((uint32_t)lr & 7) << 2)) * 4;

    // ldmatrix geometry
    const int quad = lane >> 3, l8 = lane & 7;
    const int arow = ((quad & 1) << 3) + l8;
    const uint32_t kcA = (uint32_t)((quad & 2) << 1);
    const int brow = ((quad & 2) << 2) + l8;
    const uint32_t kcB = (uint32_t)((quad & 1) << 2);

    const uint32_t aoff = (uint32_t)(wM * 16 + arow) * 128;
    const uint32_t swzA = ((uint32_t)(arow & 7)) << 2;
    const uint32_t boff = WOFF + (uint32_t)(wN * 16 + brow) * 128;
    const uint32_t swzB = ((uint32_t)(brow & 7)) << 2;

    const int S = K >> 5;
    float4 pa[AQ];

    auto ldA = [&](int s) {
        #pragma unroll
        for (int q = 0; q < AQ; q++) {
            const int row = lr + q * (NT / 8);
            pa[q] = *(const float4*)(A + (size_t)(m0 + row) * K + (s << 5) + lc4);
        }
    };
    auto cpW = [&](int s, int b) {
        const uint32_t d0 = sb + (uint32_t)b * STRIDE + WOFF;
        #pragma unroll
        for (int q = 0; q < WQ; q++) {
            const int row = lr + q * (NT / 8);
            const float* wh = Whi + (size_t)(n0 + row) * K + (s << 5) + lc4;
            const float* wl = Wlo + (size_t)(n0 + row) * K + (s << 5) + lc4;
            const uint32_t d = d0 + (uint32_t)row * 128 + ssc;
            cp16(d,      wh);
            cp16(d + WB, wl);
        }
        asm volatile("cp.async.commit_group;" ::: "memory");
    };
    auto stA = [&](int b) {
        const uint32_t d0 = sb + (uint32_t)b * STRIDE;
        #pragma unroll
        for (int q = 0; q < AQ; q++) {
            const int row = lr + q * (NT / 8);
            const uint32_t d = d0 + (uint32_t)row * 128 + ssc;
            uint32_t hx, hy, hz, hw, lx, ly, lz, lw;
            tf32split(pa[q].x, hx, lx); tf32split(pa[q].y, hy, ly);
            tf32split(pa[q].z, hz, lz); tf32split(pa[q].w, hw, lw);
            sts128(d,      hx, hy, hz, hw);
            sts128(d + AB, lx, ly, lz, lw);
        }
    };

    float acc[2][4];
    #pragma unroll
    for (int nt = 0; nt < 2; nt++)
        #pragma unroll
        for (int q = 0; q < 4; q++) acc[nt][q] = 0.0f;

    ldA(0);
    cpW(0, 0);

    for (int s = 0; s < S; s++) {
        const int b = s & 1;
        stA(b);
        asm volatile("cp.async.wait_group 0;" ::: "memory");
        __syncthreads();
        if (s + 1 < S) { ldA(s + 1); cpW(s + 1, b ^ 1); }

        const uint32_t base = sb + (uint32_t)b * STRIDE;
        uint32_t ah[2][4], al[2][4], bh[2][4], bl[2][4];

        auto ldfrag = [&](int j, int fb) {
            const uint32_t colA = (((8u * j) | kcA) ^ swzA) * 4;
            const uint32_t colB = (((8u * j) | kcB) ^ swzB) * 4;
            ldm4(ah[fb], base + aoff + colA);
            ldm4(al[fb], base + AB + aoff + colA);
            ldm4(bh[fb], base + boff + colB);
            ldm4(bl[fb], base + WB + boff + colB);
        };

        ldfrag(0, 0);
        #pragma unroll
        for (int j = 0; j < 4; j++) {
            const int fb = j & 1;
            if (j < 3) ldfrag(j + 1, fb ^ 1);
            mma8(acc[0], ah[fb], bh[fb][0], bh[fb][1]);
            mma8(acc[1], ah[fb], bh[fb][2], bh[fb][3]);
            mma8(acc[0], ah[fb], bl[fb][0], bl[fb][1]);
            mma8(acc[1], ah[fb], bl[fb][2], bl[fb][3]);
            mma8(acc[0], al[fb], bh[fb][0], bh[fb][1]);
            mma8(acc[1], al[fb], bh[fb][2], bh[fb][3]);
        }
        __syncthreads();
    }

    // ---- epilogue ----
    #pragma unroll
    for (int nt = 0; nt < 2; nt++) {
        const int col  = n0 + wN * 16 + nt * 8 + 2 * c;
        const float b0v = bias[col], b1v = bias[col + 1];
        const int row0 = m0 + wM * 16 + g;
        #pragma unroll
        for (int hh = 0; hh < 2; hh++) {
            const int row = row0 + 8 * hh;
            float v0 = acc[nt][2 * hh + 0] + b0v;
            float v1 = acc[nt][2 * hh + 1] + b1v;
            const size_t idx = (size_t)row * N + col;
            if (MODE == 0) {
                v0 = fmaxf(v0, 0.0f); v1 = fmaxf(v1, 0.0f);
                *(float2*)(C + idx) = make_float2(v0, v1);
            } else {
                *(float2*)(C + idx) = make_float2(v0, v1);
                float a0 = ep.yin[idx]     + ep.cself * v0;
                float a1 = ep.yin[idx + 1] + ep.cself * v1;
                for (int t = 0; t < ep.nks; t++) {
                    a0 += ep.cks[t] * ep.ks[t][idx];
                    a1 += ep.cks[t] * ep.ks[t][idx + 1];
                }
                *(float2*)(ep.aux + idx) = make_float2(a0, a1);
                if (ep.emit) {
                    const size_t o = (size_t)row * (10 * DD) + (size_t)ep.t * DD + col;
                    *(float2*)(ep.emit + o) = make_float2(a0, a1);
                }
            }
        }
    }
}

// Split W into tf32 hi/lo parts
__global__ void wsplit_kernel(const float* __restrict__ W,
                              float* __restrict__ hi, float* __restrict__ lo, int n)
{
    int i = blockIdx.x * blockDim.x + threadIdx.x;
    if (i < n) {
        uint32_t h, l;
        tf32split(W[i], h, l);
        hi[i] = __uint_as_float(h);
        lo[i] = __uint_as_float(l);
    }
}

extern "C" void kernel_launch(void* const* d_in, const int* in_sizes, int n_in,
                              void* d_out, int out_size)
{
    (void)in_sizes; (void)n_in; (void)out_size;
    const float* x0 = (const float*)d_in[0];
    // d_in[1] is T (int32, always 11) — baked into the graph.
    const float* W1 = (const float*)d_in[2];
    const float* b1 = (const float*)d_in[3];
    const float* W2 = (const float*)d_in[4];
    const float* b2 = (const float*)d_in[5];
    const float* W3 = (const float*)d_in[6];
    const float* b3 = (const float*)d_in[7];
    float* out = (float*)d_out;

    float *y, *ycmb, *h1, *h2, *kbase;
    float *w1h, *w1l, *w2h, *w2l, *w3h, *w3l;
    cudaGetSymbolAddress((void**)&y,     g_y);
    cudaGetSymbolAddress((void**)&ycmb,  g_ycmb);
    cudaGetSymbolAddress((void**)&h1,    g_h1);
    cudaGetSymbolAddress((void**)&h2,    g_h2);
    cudaGetSymbolAddress((void**)&kbase, g_k);
    cudaGetSymbolAddress((void**)&w1h,   g_W1hi);
    cudaGetSymbolAddress((void**)&w1l,   g_W1lo);
    cudaGetSymbolAddress((void**)&w2h,   g_W2hi);
    cudaGetSymbolAddress((void**)&w2l,   g_W2lo);
    cudaGetSymbolAddress((void**)&w3h,   g_W3hi);
    cudaGetSymbolAddress((void**)&w3l,   g_W3lo);
    float* k[6];
    for (int j = 0; j < 6; j++) k[j] = kbase + (size_t)j * BB * DD;

    // smem: 2 * STRIDE bytes
    const int SM12 = 2 * (2 * 32 * 128 + 2 * 64 * 128);   // 49152
    const int SM3  = 2 * (2 * 32 * 128 + 2 * 32 * 128);   // 32768
    cudaFuncSetAttribute((const void*)&gemm_tc<32, 64, 4, 0>,
                         cudaFuncAttributeMaxDynamicSharedMemorySize, SM12);
    cudaFuncSetAttribute((const void*)&gemm_tc<32, 32, 2, 1>,
                         cudaFuncAttributeMaxDynamicSharedMemorySize, SM3);

    // y = x0[:,0,:]
    cudaMemcpyAsync(y, x0, sizeof(float) * BB * DD, cudaMemcpyDeviceToDevice);

    wsplit_kernel<<<(HH * DD + 255) / 256, 256>>>(W1, w1h, w1l, HH * DD);
    wsplit_kernel<<<(HH * HH + 255) / 256, 256>>>(W2, w2h, w2l, HH * HH);
    wsplit_kernel<<<(DD * HH + 255) / 256, 256>>>(W3, w3h, w3l, DD * HH);

    // Dopri5 tableau
    const double A2[] = {1.0/5.0};
    const double A3[] = {3.0/40.0, 9.0/40.0};
    const double A4[] = {44.0/45.0, -56.0/15.0, 32.0/9.0};
    const double A5[] = {19372.0/6561.0, -25360.0/2187.0, 64448.0/6561.0, -212.0/729.0};
    const double A6[] = {9017.0/3168.0, -355.0/33.0, 46732.0/5247.0, 49.0/176.0, -5103.0/18656.0};
    const double* Arows[5] = {A2, A3, A4, A5, A6};

    const dim3 grd1(HH / 64, BB / 32);   // 8 x 32 = 256 CTAs (256 thr)
    const dim3 grd2(HH / 64, BB / 32);   // 256 CTAs
    const dim3 grd3(DD / 32, BB / 32);   // 8 x 32 = 256 CTAs (128 thr)

    Epi enone = {};

    for (int step = 0; step < N_STEPS; step++) {
        for (int s = 0; s < 6; s++) {
            const float* Ain = (s == 0) ? y : ycmb;
            gemm_tc<32, 64, 4, 0><<<grd1, 256, SM12>>>(Ain, w1h, w1l, b1, h1, DD, HH, enone);
            gemm_tc<32, 64, 4, 0><<<grd2, 256, SM12>>>(h1,  w2h, w2l, b2, h2, HH, HH, enone);

            Epi ep = {};
            ep.yin = y;
            if (s < 5) {
                const double* row = Arows[s];
                ep.nks = s;
                for (int j = 0; j < s; j++) {
                    ep.ks[j]  = k[j];
                    ep.cks[j] = (float)((double)HSTEP * row[j]);
                }
                ep.cself = (float)((double)HSTEP * row[s]);
                ep.aux   = ycmb;
                ep.emit  = nullptr;
                ep.t     = 0;
            } else {
                ep.nks = 4;
                ep.ks[0] = k[0]; ep.cks[0] = (float)((double)HSTEP * (35.0 / 384.0));
                ep.ks[1] = k[2]; ep.cks[1] = (float)((double)HSTEP * (500.0 / 1113.0));
                ep.ks[2] = k[3]; ep.cks[2] = (float)((double)HSTEP * (125.0 / 192.0));
                ep.ks[3] = k[4]; ep.cks[3] = (float)((double)HSTEP * (-2187.0 / 6784.0));
                ep.cself = (float)((double)HSTEP * (11.0 / 84.0));
                ep.aux   = y;
                ep.emit  = ((step & 3) == 3) ? out : nullptr;
                ep.t     = step >> 2;
            }
            gemm_tc<32, 32, 2, 1><<<grd3, 128, SM3>>>(h2, w3h, w3l, b3, k[s], HH, DD, ep);
        }
    }
}

// round 9
// speedup vs baseline: 1.1710x; 1.1710x over previous
#include <cuda_runtime.h>
#include <cstdint>
#include <cstddef>

// ---------------------------------------------------------------------------
// NeuralODE Dopri5. GEMMs: mma.sync m16n8k8 TF32, 3xTF32 split.
// BK=64 stages, TRIPLE-buffered smem, 2-stage lookahead for both A (LDG ->
// split -> STS) and W (pre-split, cp.async, wait_group 1). One barrier/stage.
// 8 warps, warp tile 32x16 (MT=2) for L1/L2; 16x16 (MT=1) for L3.
// RK combine fused into layer-3 epilogue.
// ---------------------------------------------------------------------------

#define BB 1024
#define DD 256
#define HH 512
#define N_STEPS 40
#define HSTEP 0.25f

__device__ float g_y   [BB * DD];
__device__ float g_ycmb[BB * DD];
__device__ float g_k [6][BB * DD];
__device__ float g_h1[BB * HH];
__device__ float g_h2[BB * HH];
__device__ float g_W1hi[HH * DD], g_W1lo[HH * DD];
__device__ float g_W2hi[HH * HH], g_W2lo[HH * HH];
__device__ float g_W3hi[DD * HH], g_W3lo[DD * HH];

struct Epi {
    const float* yin;
    const float* ks[4];
    float        cks[4];
    int          nks;
    float        cself;
    float*       aux;
    float*       emit;
    int          t;
};

// ----------------------------- helpers -------------------------------------
__device__ __forceinline__ uint32_t smem_u32(const void* p) {
    uint32_t a;
    asm("{ .reg .u64 t; cvta.to.shared.u64 t, %1; cvt.u32.u64 %0, t; }"
        : "=r"(a) : "l"(p));
    return a;
}
__device__ __forceinline__ void tf32split(float x, uint32_t& hi, uint32_t& lo) {
    uint32_t h; asm("cvt.rna.tf32.f32 %0, %1;" : "=r"(h) : "f"(x));
    float r = x - __uint_as_float(h);
    asm("cvt.rna.tf32.f32 %0, %1;" : "=r"(lo) : "f"(r));
    hi = h;
}
__device__ __forceinline__ void sts128(uint32_t a, uint32_t x, uint32_t y,
                                       uint32_t z, uint32_t w) {
    asm volatile("st.shared.v4.b32 [%0], {%1,%2,%3,%4};"
                 :: "r"(a), "r"(x), "r"(y), "r"(z), "r"(w) : "memory");
}
__device__ __forceinline__ void cp16(uint32_t d, const float* s) {
    asm volatile("cp.async.cg.shared.global [%0], [%1], 16;"
                 :: "r"(d), "l"(s) : "memory");
}
__device__ __forceinline__ void cp_commit() {
    asm volatile("cp.async.commit_group;" ::: "memory");
}
__device__ __forceinline__ void cp_wait1() {
    asm volatile("cp.async.wait_group 1;" ::: "memory");
}
__device__ __forceinline__ void ldm4(uint32_t* r, uint32_t addr) {
    asm volatile("ldmatrix.sync.aligned.m8n8.x4.shared.b16 {%0,%1,%2,%3}, [%4];"
                 : "=r"(r[0]), "=r"(r[1]), "=r"(r[2]), "=r"(r[3]) : "r"(addr));
}
__device__ __forceinline__ void mma8(float* d, const uint32_t* a,
                                     uint32_t b0, uint32_t b1) {
    asm volatile(
        "mma.sync.aligned.m16n8k8.row.col.f32.tf32.tf32.f32 "
        "{%0,%1,%2,%3}, {%4,%5,%6,%7}, {%8,%9}, {%0,%1,%2,%3};"
        : "+f"(d[0]), "+f"(d[1]), "+f"(d[2]), "+f"(d[3])
        : "r"(a[0]), "r"(a[1]), "r"(a[2]), "r"(a[3]), "r"(b0), "r"(b1));
}

// ---------------------------------------------------------------------------
// GEMM: C[M,N] = act(A @ W^T + bias). 256 threads, warp grid 2(M) x 4(N),
// warp tile (16*MT) x 16, CTA tile (32*MT) x 64. BK=64 (two 32-col sub-tiles
// per stage), 3 smem buffers, 2-stage lookahead, one barrier per stage.
// Smem rows 128B with XOR swizzle col4 ^= 4*(row&7).
// Stage buffer: Ahi[AB] Alo[AB] Whi[WB] Wlo[WB], AB=BM*256, WB=64*256.
// MODE 0: relu fp32 store. MODE 1: linear store + fused RK-combine epilogue.
// ---------------------------------------------------------------------------
template<int MT, int MODE>
__global__ __launch_bounds__(256, 1)
void gemm_tc(const float* __restrict__ A,
             const float* __restrict__ Whi, const float* __restrict__ Wlo,
             const float* __restrict__ bias, float* __restrict__ C,
             int K, int N, Epi ep)
{
    constexpr int BM = 32 * MT;
    constexpr uint32_t AB = (uint32_t)BM * 256;      // bytes per A part
    constexpr uint32_t WB = 64 * 256;                // bytes per W part
    constexpr uint32_t ASUB = (uint32_t)BM * 128;    // A sub-tile stride
    constexpr uint32_t WSUB = 64 * 128;              // W sub-tile stride
    constexpr uint32_t WOFFS = 2 * AB;
    constexpr uint32_t STRIDE = 2 * AB + 2 * WB;

    extern __shared__ float smem[];
    const uint32_t sb = smem_u32(smem);
    const int tid  = threadIdx.x;
    const int warp = tid >> 5, lane = tid & 31;
    const int wM = warp >> 2, wN = warp & 3;
    const int g = lane >> 2, c = lane & 3;
    const int m0 = blockIdx.y * BM, n0 = blockIdx.x * 64;

    // loader geometry
    const int lr  = tid >> 3;                        // 0..31
    const int lc4 = (tid & 7) * 4;
    const uint32_t ssc = ((uint32_t)lc4 ^ (((uint32_t)lr & 7) << 2)) * 4;

    // ldmatrix geometry
    const int quad = lane >> 3, l8 = lane & 7;
    const int arow = ((quad & 1) << 3) + l8;
    const uint32_t kcA = (uint32_t)((quad & 2) << 1);
    const int brow = ((quad & 2) << 2) + l8;
    const uint32_t kcB = (uint32_t)((quad & 1) << 2);

    uint32_t aoff[MT];
    #pragma unroll
    for (int i = 0; i < MT; i++)
        aoff[i] = (uint32_t)(wM * 16 * MT + i * 16 + arow) * 128;
    const uint32_t swzA = ((uint32_t)(arow & 7)) << 2;
    const uint32_t boff = (uint32_t)(wN * 16 + brow) * 128;
    const uint32_t swzB = ((uint32_t)(brow & 7)) << 2;

    const int S = K >> 6;                            // BK=64 stages
    float4 pa[2][MT];                                // [sub-tile][row-group]

    auto ldA = [&](int s) {
        #pragma unroll
        for (int t = 0; t < 2; t++)
            #pragma unroll
            for (int q = 0; q < MT; q++) {
                const int row = lr + q * 32;
                pa[t][q] = *(const float4*)(A + (size_t)(m0 + row) * K
                                            + (s << 6) + t * 32 + lc4);
            }
    };
    auto stA = [&](int buf) {
        const uint32_t b0 = sb + (uint32_t)buf * STRIDE;
        #pragma unroll
        for (int t = 0; t < 2; t++)
            #pragma unroll
            for (int q = 0; q < MT; q++) {
                const int row = lr + q * 32;
                const uint32_t d = b0 + (uint32_t)t * ASUB
                                 + (uint32_t)row * 128 + ssc;
                uint32_t hx, hy, hz, hw, lx, ly, lz, lw;
                tf32split(pa[t][q].x, hx, lx); tf32split(pa[t][q].y, hy, ly);
                tf32split(pa[t][q].z, hz, lz); tf32split(pa[t][q].w, hw, lw);
                sts128(d,      hx, hy, hz, hw);
                sts128(d + AB, lx, ly, lz, lw);
            }
    };
    auto cpW = [&](int s, int buf) {
        const uint32_t w0 = sb + (uint32_t)buf * STRIDE + WOFFS;
        #pragma unroll
        for (int t = 0; t < 2; t++)
            #pragma unroll
            for (int q = 0; q < 2; q++) {
                const int row = lr + q * 32;
                const size_t off = (size_t)(n0 + row) * K + (s << 6) + t * 32 + lc4;
                const uint32_t d = w0 + (uint32_t)t * WSUB
                                 + (uint32_t)row * 128 + ssc;
                cp16(d,      Whi + off);
                cp16(d + WB, Wlo + off);
            }
    };

    float acc[MT][2][4];
    #pragma unroll
    for (int i = 0; i < MT; i++)
        #pragma unroll
        for (int nt = 0; nt < 2; nt++)
            #pragma unroll
            for (int q = 0; q < 4; q++) acc[i][nt][q] = 0.0f;

    // prologue: A(0) staged into buf0, A(1) in regs; W(0)->buf0, W(1)->buf1
    ldA(0);
    stA(0);
    ldA(1);
    cpW(0, 0); cp_commit();
    cpW(1, 1); cp_commit();

    int cur = 0, nxt = 1, nx2 = 2;

    for (int s = 0; s < S; s++) {
        cp_wait1();              // W(s) resident
        __syncthreads();         // A(s) visible; prior reads of nxt/nx2 done

        if (s + 1 < S) stA(nxt);             // pa holds A(s+1)
        if (s + 2 < S) { ldA(s + 2); cpW(s + 2, nx2); }
        cp_commit();

        const uint32_t base = sb + (uint32_t)cur * STRIDE;
        uint32_t ah[2][MT][4], al[2][MT][4], bh[2][4], bl[2][4];

        auto ldfrag = [&](int j, int fb) {
            const int t = j >> 2, jj = j & 3;
            const uint32_t colA = (((8u * jj) | kcA) ^ swzA) * 4;
            const uint32_t colB = (((8u * jj) | kcB) ^ swzB) * 4;
            const uint32_t ab = base + (uint32_t)t * ASUB;
            const uint32_t wb = base + WOFFS + (uint32_t)t * WSUB;
            #pragma unroll
            for (int i = 0; i < MT; i++) {
                ldm4(ah[fb][i], ab + aoff[i] + colA);
                ldm4(al[fb][i], ab + AB + aoff[i] + colA);
            }
            ldm4(bh[fb], wb + boff + colB);
            ldm4(bl[fb], wb + WB + boff + colB);
        };

        ldfrag(0, 0);
        #pragma unroll
        for (int j = 0; j < 8; j++) {
            const int fb = j & 1;
            if (j < 7) ldfrag(j + 1, fb ^ 1);
            #pragma unroll
            for (int i = 0; i < MT; i++) {
                mma8(acc[i][0], ah[fb][i], bh[fb][0], bh[fb][1]);
                mma8(acc[i][1], ah[fb][i], bh[fb][2], bh[fb][3]);
                mma8(acc[i][0], ah[fb][i], bl[fb][0], bl[fb][1]);
                mma8(acc[i][1], ah[fb][i], bl[fb][2], bl[fb][3]);
                mma8(acc[i][0], al[fb][i], bh[fb][0], bh[fb][1]);
                mma8(acc[i][1], al[fb][i], bh[fb][2], bh[fb][3]);
            }
        }

        const int tmp = cur; cur = nxt; nxt = nx2; nx2 = tmp;
    }

    // ---- epilogue ----
    #pragma unroll
    for (int i = 0; i < MT; i++) {
        #pragma unroll
        for (int nt = 0; nt < 2; nt++) {
            const int col  = n0 + wN * 16 + nt * 8 + 2 * c;
            const float b0v = bias[col], b1v = bias[col + 1];
            const int row0 = m0 + wM * 16 * MT + i * 16 + g;
            #pragma unroll
            for (int hh = 0; hh < 2; hh++) {
                const int row = row0 + 8 * hh;
                float v0 = acc[i][nt][2 * hh + 0] + b0v;
                float v1 = acc[i][nt][2 * hh + 1] + b1v;
                const size_t idx = (size_t)row * N + col;
                if (MODE == 0) {
                    v0 = fmaxf(v0, 0.0f); v1 = fmaxf(v1, 0.0f);
                    *(float2*)(C + idx) = make_float2(v0, v1);
                } else {
                    *(float2*)(C + idx) = make_float2(v0, v1);
                    float a0 = ep.yin[idx]     + ep.cself * v0;
                    float a1 = ep.yin[idx + 1] + ep.cself * v1;
                    for (int t = 0; t < ep.nks; t++) {
                        a0 += ep.cks[t] * ep.ks[t][idx];
                        a1 += ep.cks[t] * ep.ks[t][idx + 1];
                    }
                    *(float2*)(ep.aux + idx) = make_float2(a0, a1);
                    if (ep.emit) {
                        const size_t o = (size_t)row * (10 * DD) + (size_t)ep.t * DD + col;
                        *(float2*)(ep.emit + o) = make_float2(a0, a1);
                    }
                }
            }
        }
    }
}

// Split W into tf32 hi/lo parts
__global__ void wsplit_kernel(const float* __restrict__ W,
                              float* __restrict__ hi, float* __restrict__ lo, int n)
{
    int i = blockIdx.x * blockDim.x + threadIdx.x;
    if (i < n) {
        uint32_t h, l;
        tf32split(W[i], h, l);
        hi[i] = __uint_as_float(h);
        lo[i] = __uint_as_float(l);
    }
}

extern "C" void kernel_launch(void* const* d_in, const int* in_sizes, int n_in,
                              void* d_out, int out_size)
{
    (void)in_sizes; (void)n_in; (void)out_size;
    const float* x0 = (const float*)d_in[0];
    // d_in[1] is T (int32, always 11) — baked into the graph.
    const float* W1 = (const float*)d_in[2];
    const float* b1 = (const float*)d_in[3];
    const float* W2 = (const float*)d_in[4];
    const float* b2 = (const float*)d_in[5];
    const float* W3 = (const float*)d_in[6];
    const float* b3 = (const float*)d_in[7];
    float* out = (float*)d_out;

    float *y, *ycmb, *h1, *h2, *kbase;
    float *w1h, *w1l, *w2h, *w2l, *w3h, *w3l;
    cudaGetSymbolAddress((void**)&y,     g_y);
    cudaGetSymbolAddress((void**)&ycmb,  g_ycmb);
    cudaGetSymbolAddress((void**)&h1,    g_h1);
    cudaGetSymbolAddress((void**)&h2,    g_h2);
    cudaGetSymbolAddress((void**)&kbase, g_k);
    cudaGetSymbolAddress((void**)&w1h,   g_W1hi);
    cudaGetSymbolAddress((void**)&w1l,   g_W1lo);
    cudaGetSymbolAddress((void**)&w2h,   g_W2hi);
    cudaGetSymbolAddress((void**)&w2l,   g_W2lo);
    cudaGetSymbolAddress((void**)&w3h,   g_W3hi);
    cudaGetSymbolAddress((void**)&w3l,   g_W3lo);
    float* k[6];
    for (int j = 0; j < 6; j++) k[j] = kbase + (size_t)j * BB * DD;

    // 3 buffers: STRIDE = 2*AB + 2*WB
    const int SM12 = 3 * (2 * 64 * 256 + 2 * 64 * 256);   // MT=2: 196608
    const int SM3  = 3 * (2 * 32 * 256 + 2 * 64 * 256);   // MT=1: 147456
    cudaFuncSetAttribute((const void*)&gemm_tc<2, 0>,
                         cudaFuncAttributeMaxDynamicSharedMemorySize, SM12);
    cudaFuncSetAttribute((const void*)&gemm_tc<1, 1>,
                         cudaFuncAttributeMaxDynamicSharedMemorySize, SM3);

    // y = x0[:,0,:]
    cudaMemcpyAsync(y, x0, sizeof(float) * BB * DD, cudaMemcpyDeviceToDevice);

    wsplit_kernel<<<(HH * DD + 255) / 256, 256>>>(W1, w1h, w1l, HH * DD);
    wsplit_kernel<<<(HH * HH + 255) / 256, 256>>>(W2, w2h, w2l, HH * HH);
    wsplit_kernel<<<(DD * HH + 255) / 256, 256>>>(W3, w3h, w3l, DD * HH);

    // Dopri5 tableau
    const double A2[] = {1.0/5.0};
    const double A3[] = {3.0/40.0, 9.0/40.0};
    const double A4[] = {44.0/45.0, -56.0/15.0, 32.0/9.0};
    const double A5[] = {19372.0/6561.0, -25360.0/2187.0, 64448.0/6561.0, -212.0/729.0};
    const double A6[] = {9017.0/3168.0, -355.0/33.0, 46732.0/5247.0, 49.0/176.0, -5103.0/18656.0};
    const double* Arows[5] = {A2, A3, A4, A5, A6};

    const dim3 grd1(HH / 64, BB / 64);   // 8 x 16 = 128 CTAs
    const dim3 grd2(HH / 64, BB / 64);   // 128 CTAs
    const dim3 grd3(DD / 64, BB / 32);   // 4 x 32 = 128 CTAs

    Epi enone = {};

    for (int step = 0; step < N_STEPS; step++) {
        for (int s = 0; s < 6; s++) {
            const float* Ain = (s == 0) ? y : ycmb;
            gemm_tc<2, 0><<<grd1, 256, SM12>>>(Ain, w1h, w1l, b1, h1, DD, HH, enone);
            gemm_tc<2, 0><<<grd2, 256, SM12>>>(h1,  w2h, w2l, b2, h2, HH, HH, enone);

            Epi ep = {};
            ep.yin = y;
            if (s < 5) {
                const double* row = Arows[s];
                ep.nks = s;
                for (int j = 0; j < s; j++) {
                    ep.ks[j]  = k[j];
                    ep.cks[j] = (float)((double)HSTEP * row[j]);
                }
                ep.cself = (float)((double)HSTEP * row[s]);
                ep.aux   = ycmb;
                ep.emit  = nullptr;
                ep.t     = 0;
            } else {
                ep.nks = 4;
                ep.ks[0] = k[0]; ep.cks[0] = (float)((double)HSTEP * (35.0 / 384.0));
                ep.ks[1] = k[2]; ep.cks[1] = (float)((double)HSTEP * (500.0 / 1113.0));
                ep.ks[2] = k[3]; ep.cks[2] = (float)((double)HSTEP * (125.0 / 192.0));
                ep.ks[3] = k[4]; ep.cks[3] = (float)((double)HSTEP * (-2187.0 / 6784.0));
                ep.cself = (float)((double)HSTEP * (11.0 / 84.0));
                ep.aux   = y;
                ep.emit  = ((step & 3) == 3) ? out : nullptr;
                ep.t     = step >> 2;
            }
            gemm_tc<1, 1><<<grd3, 256, SM3>>>(h2, w3h, w3l, b3, k[s], HH, DD, ep);
        }
    }
}